// round 1
// baseline (speedup 1.0000x reference)
#include <cuda_runtime.h>
#include <cuda_bf16.h>
#include <math.h>

#define B_ 16
#define I_ 512
#define O_ 512
#define T_ 256
#define L_ 4096
#define EPS_ 1e-8f

// Scratch: modulation scales s[B,I] and demodulated per-sample weights bw[B,O,I]
__device__ float g_s[B_ * I_];
__device__ float g_bw[B_ * O_ * I_];   // 16 MB fp32

// ---------------------------------------------------------------------------
// Kernel 1: modulation MLP.  One block per batch element, 256 threads.
// h1 = silu(t@W1^T + b1); h2 = silu(h1@W2^T + b2); s = h2@W3^T + b3 + 1
// ---------------------------------------------------------------------------
__global__ void mlp_kernel(const float* __restrict__ t,
                           const float* __restrict__ W1, const float* __restrict__ b1,
                           const float* __restrict__ W2, const float* __restrict__ b2,
                           const float* __restrict__ W3, const float* __restrict__ b3) {
    __shared__ float tb[T_];
    __shared__ float h1[T_];
    __shared__ float h2[T_];
    const int b = blockIdx.x;
    const int j = threadIdx.x;          // 0..255

    tb[j] = t[b * T_ + j];
    __syncthreads();

    // h1[j]
    {
        float acc = b1[j];
        const float* wrow = W1 + j * T_;
        #pragma unroll 8
        for (int k = 0; k < T_; k++) acc += tb[k] * wrow[k];
        h1[j] = acc / (1.0f + expf(-acc));   // silu
    }
    __syncthreads();

    // h2[j]
    {
        float acc = b2[j];
        const float* wrow = W2 + j * T_;
        #pragma unroll 8
        for (int k = 0; k < T_; k++) acc += h1[k] * wrow[k];
        h2[j] = acc / (1.0f + expf(-acc));
    }
    __syncthreads();

    // s[i], two outputs per thread (I_ = 512)
    #pragma unroll
    for (int r = 0; r < 2; r++) {
        const int i = j + r * 256;
        float acc = b3[i] + 1.0f;
        const float* wrow = W3 + i * T_;
        #pragma unroll 8
        for (int k = 0; k < T_; k++) acc += h2[k] * wrow[k];
        g_s[b * I_ + i] = acc;
    }
}

// ---------------------------------------------------------------------------
// Kernel 2: demodulation.  One block per (o, b), 128 threads.
// bw[b,o,i] = weight[o,i]*s[b,i] * rsqrt(sum_i (weight[o,i]*s[b,i])^2 + eps)
// ---------------------------------------------------------------------------
__global__ void demod_kernel(const float* __restrict__ weight) {
    const int o = blockIdx.x;
    const int b = blockIdx.y;
    const int tid = threadIdx.x;        // 0..127
    const float* srow = g_s + b * I_;
    const float* wrow = weight + o * I_;

    float v[4];
    float ss = 0.0f;
    #pragma unroll
    for (int r = 0; r < 4; r++) {
        const int i = tid + r * 128;
        const float val = wrow[i] * srow[i];
        v[r] = val;
        ss += val * val;
    }
    // warp reduce
    #pragma unroll
    for (int off = 16; off > 0; off >>= 1)
        ss += __shfl_xor_sync(0xFFFFFFFFu, ss, off);
    __shared__ float red[4];
    if ((tid & 31) == 0) red[tid >> 5] = ss;
    __syncthreads();
    const float total = red[0] + red[1] + red[2] + red[3];
    const float d = rsqrtf(total + EPS_);

    float* brow = g_bw + ((size_t)b * O_ + o) * I_;
    #pragma unroll
    for (int r = 0; r < 4; r++)
        brow[tid + r * 128] = v[r] * d;
}

// ---------------------------------------------------------------------------
// Kernel 3: batched SGEMM  out[b] = bw[b] (512x512) @ x[b] (512x4096)
// 128x128 tile, BK=16, 256 threads, 8x8 per-thread microtile.
// ---------------------------------------------------------------------------
__global__ __launch_bounds__(256, 2)
void gemm_kernel(const float* __restrict__ x, float* __restrict__ out) {
    __shared__ __align__(16) float As[16][132];   // [k][m], padded row (132*4=528=33*16)
    __shared__ __align__(16) float Bs[16][128];   // [k][l]

    const int b  = blockIdx.z;
    const int o0 = blockIdx.y * 128;
    const int l0 = blockIdx.x * 128;

    const float* A  = g_bw + (size_t)b * O_ * I_;        // [512,512]
    const float* Bx = x    + (size_t)b * I_ * L_;        // [512,4096]
    float*       C  = out  + (size_t)b * O_ * L_;

    const int tid = threadIdx.x;
    const int tx = tid & 15;            // l microtile index
    const int ty = tid >> 4;            // o microtile index

    // A-tile load mapping: 128 rows x 16 cols -> 2 float4 per thread
    const int aRow = tid >> 2;          // 0..63
    const int aCol = (tid & 3) * 4;     // 0,4,8,12
    // B-tile load mapping: 16 rows x 128 cols -> 2 float4 per thread
    const int bRow = tid >> 5;          // 0..7
    const int bCol = (tid & 31) * 4;    // 0..124

    float acc[8][8];
    #pragma unroll
    for (int i = 0; i < 8; i++)
        #pragma unroll
        for (int j = 0; j < 8; j++) acc[i][j] = 0.0f;

    for (int k0 = 0; k0 < I_; k0 += 16) {
        const float4 a0 = *(const float4*)&A[(size_t)(o0 + aRow)      * I_ + k0 + aCol];
        const float4 a1 = *(const float4*)&A[(size_t)(o0 + aRow + 64) * I_ + k0 + aCol];
        const float4 x0 = *(const float4*)&Bx[(size_t)(k0 + bRow)     * L_ + l0 + bCol];
        const float4 x1 = *(const float4*)&Bx[(size_t)(k0 + bRow + 8) * L_ + l0 + bCol];

        __syncthreads();   // previous iteration's compute done before overwrite

        As[aCol + 0][aRow] = a0.x;  As[aCol + 1][aRow] = a0.y;
        As[aCol + 2][aRow] = a0.z;  As[aCol + 3][aRow] = a0.w;
        As[aCol + 0][aRow + 64] = a1.x;  As[aCol + 1][aRow + 64] = a1.y;
        As[aCol + 2][aRow + 64] = a1.z;  As[aCol + 3][aRow + 64] = a1.w;
        *(float4*)&Bs[bRow][bCol]     = x0;
        *(float4*)&Bs[bRow + 8][bCol] = x1;

        __syncthreads();

        #pragma unroll
        for (int kk = 0; kk < 16; kk++) {
            float4 ar0 = *(const float4*)&As[kk][ty * 8];
            float4 ar1 = *(const float4*)&As[kk][ty * 8 + 4];
            float4 br0 = *(const float4*)&Bs[kk][tx * 8];
            float4 br1 = *(const float4*)&Bs[kk][tx * 8 + 4];
            const float ar[8] = {ar0.x, ar0.y, ar0.z, ar0.w, ar1.x, ar1.y, ar1.z, ar1.w};
            const float br[8] = {br0.x, br0.y, br0.z, br0.w, br1.x, br1.y, br1.z, br1.w};
            #pragma unroll
            for (int i = 0; i < 8; i++)
                #pragma unroll
                for (int j = 0; j < 8; j++)
                    acc[i][j] += ar[i] * br[j];
        }
    }

    // Epilogue: 8 rows x 2 float4 per thread
    #pragma unroll
    for (int i = 0; i < 8; i++) {
        const int o = o0 + ty * 8 + i;
        float* crow = C + (size_t)o * L_ + l0 + tx * 8;
        float4 v0 = {acc[i][0], acc[i][1], acc[i][2], acc[i][3]};
        float4 v1 = {acc[i][4], acc[i][5], acc[i][6], acc[i][7]};
        *(float4*)&crow[0] = v0;
        *(float4*)&crow[4] = v1;
    }
}

// ---------------------------------------------------------------------------
extern "C" void kernel_launch(void* const* d_in, const int* in_sizes, int n_in,
                              void* d_out, int out_size) {
    const float* x      = (const float*)d_in[0];   // [16,512,4096]
    const float* t      = (const float*)d_in[1];   // [16,256]
    const float* weight = (const float*)d_in[2];   // [512,512]
    const float* W1     = (const float*)d_in[3];   // [256,256]
    const float* b1     = (const float*)d_in[4];   // [256]
    const float* W2     = (const float*)d_in[5];   // [256,256]
    const float* b2     = (const float*)d_in[6];   // [256]
    const float* W3     = (const float*)d_in[7];   // [512,256]
    const float* b3     = (const float*)d_in[8];   // [512]
    float* out = (float*)d_out;                    // [16,512,4096]

    mlp_kernel<<<B_, 256>>>(t, W1, b1, W2, b2, W3, b3);
    demod_kernel<<<dim3(O_, B_), 128>>>(weight);
    gemm_kernel<<<dim3(L_ / 128, O_ / 128, B_), 256>>>(x, out);
}

// round 4
// speedup vs baseline: 2.1324x; 2.1324x over previous
#include <cuda_runtime.h>
#include <cuda_bf16.h>
#include <cstdint>
#include <math.h>

#define B_ 16
#define I_ 512
#define O_ 512
#define T_ 256
#define L_ 4096
#define EPS_ 1e-8f

// ---------------------------------------------------------------------------
// Scratch (static __device__ arrays; no runtime allocation)
// ---------------------------------------------------------------------------
__device__ float g_s[B_ * I_];
__device__ __nv_bfloat16 g_bw_hi[B_ * O_ * I_];      // 8 MB
__device__ __nv_bfloat16 g_bw_lo[B_ * O_ * I_];      // 8 MB

// ---------------------------------------------------------------------------
// Helpers
// ---------------------------------------------------------------------------
__device__ __forceinline__ uint32_t smem_u32(const void* p) {
    uint32_t a;
    asm("{ .reg .u64 t; cvta.to.shared.u64 t, %1; cvt.u32.u64 %0, t; }" : "=r"(a) : "l"(p));
    return a;
}

#define LDSM4(r, addr) \
    asm volatile("ldmatrix.sync.aligned.m8n8.x4.shared.b16 {%0,%1,%2,%3}, [%4];" \
        : "=r"((r)[0]), "=r"((r)[1]), "=r"((r)[2]), "=r"((r)[3]) : "r"(addr))

#define LDSM4T(r, addr) \
    asm volatile("ldmatrix.sync.aligned.m8n8.x4.trans.shared.b16 {%0,%1,%2,%3}, [%4];" \
        : "=r"((r)[0]), "=r"((r)[1]), "=r"((r)[2]), "=r"((r)[3]) : "r"(addr))

#define MMA_BF16(acc, a, b0, b1) \
    asm volatile("mma.sync.aligned.m16n8k16.row.col.f32.bf16.bf16.f32 " \
        "{%0,%1,%2,%3}, {%4,%5,%6,%7}, {%8,%9}, {%0,%1,%2,%3};" \
        : "+f"((acc)[0]), "+f"((acc)[1]), "+f"((acc)[2]), "+f"((acc)[3]) \
        : "r"((a)[0]), "r"((a)[1]), "r"((a)[2]), "r"((a)[3]), "r"(b0), "r"(b1))

// ---------------------------------------------------------------------------
// Kernel 1: modulation MLP. 1 block/batch, 256 threads, warp-per-32-outputs,
// lanes stride over K -> fully coalesced W reads.
// ---------------------------------------------------------------------------
__global__ void mlp_kernel(const float* __restrict__ t,
                           const float* __restrict__ W1, const float* __restrict__ b1,
                           const float* __restrict__ W2, const float* __restrict__ b2,
                           const float* __restrict__ W3, const float* __restrict__ b3) {
    __shared__ float tb[T_], h1[T_], h2[T_];
    const int b = blockIdx.x;
    const int tid = threadIdx.x, wid = tid >> 5, lid = tid & 31;

    tb[tid] = t[b * T_ + tid];
    __syncthreads();

    for (int j = wid * 32; j < wid * 32 + 32; j++) {
        float acc = 0.0f;
        const float* wrow = W1 + j * T_;
        #pragma unroll
        for (int u = 0; u < 8; u++) acc += tb[lid + u * 32] * wrow[lid + u * 32];
        #pragma unroll
        for (int off = 16; off > 0; off >>= 1) acc += __shfl_xor_sync(0xFFFFFFFFu, acc, off);
        if (lid == 0) { float z = acc + b1[j]; h1[j] = z / (1.0f + expf(-z)); }
    }
    __syncthreads();

    for (int j = wid * 32; j < wid * 32 + 32; j++) {
        float acc = 0.0f;
        const float* wrow = W2 + j * T_;
        #pragma unroll
        for (int u = 0; u < 8; u++) acc += h1[lid + u * 32] * wrow[lid + u * 32];
        #pragma unroll
        for (int off = 16; off > 0; off >>= 1) acc += __shfl_xor_sync(0xFFFFFFFFu, acc, off);
        if (lid == 0) { float z = acc + b2[j]; h2[j] = z / (1.0f + expf(-z)); }
    }
    __syncthreads();

    for (int j = wid * 64; j < wid * 64 + 64; j++) {
        float acc = 0.0f;
        const float* wrow = W3 + j * T_;
        #pragma unroll
        for (int u = 0; u < 8; u++) acc += h2[lid + u * 32] * wrow[lid + u * 32];
        #pragma unroll
        for (int off = 16; off > 0; off >>= 1) acc += __shfl_xor_sync(0xFFFFFFFFu, acc, off);
        if (lid == 0) g_s[b * I_ + j] = acc + b3[j] + 1.0f;
    }
}

// ---------------------------------------------------------------------------
// Kernel 2: demodulation -> bf16 hi/lo weights, K-major [b][o][i].
// ---------------------------------------------------------------------------
__global__ void demod_kernel(const float* __restrict__ weight) {
    const int o = blockIdx.x, b = blockIdx.y;
    const int tid = threadIdx.x;  // 0..127
    const float* srow = g_s + b * I_;
    const float* wrow = weight + o * I_;

    float v[4];
    float ss = 0.0f;
    #pragma unroll
    for (int r = 0; r < 4; r++) {
        const int i = tid + r * 128;
        const float val = wrow[i] * srow[i];
        v[r] = val;
        ss += val * val;
    }
    #pragma unroll
    for (int off = 16; off > 0; off >>= 1) ss += __shfl_xor_sync(0xFFFFFFFFu, ss, off);
    __shared__ float red[4];
    if ((tid & 31) == 0) red[tid >> 5] = ss;
    __syncthreads();
    const float d = rsqrtf(red[0] + red[1] + red[2] + red[3] + EPS_);

    const size_t base = ((size_t)b * O_ + o) * I_;
    #pragma unroll
    for (int r = 0; r < 4; r++) {
        const float val = v[r] * d;
        const __nv_bfloat16 hi = __float2bfloat16(val);
        const __nv_bfloat16 lo = __float2bfloat16(val - __bfloat162float(hi));
        g_bw_hi[base + tid + r * 128] = hi;
        g_bw_lo[base + tid + r * 128] = lo;
    }
}

// ---------------------------------------------------------------------------
// Kernel 3: mma.sync batched GEMM  out[b,o,l] = sum_i bw[b,o,i] * x[b,i,l]
// Block tile 128(M=o) x 128(N=l), K chunks of 32, 512 threads (16 warps),
// warp tile 32x32. bf16 hi/lo 3-MMA split, fp32 accum.
// x converted fp32 -> bf16 hi/lo on the fly during SMEM staging.
// ---------------------------------------------------------------------------
#define PA 40                      // A smem pitch (bf16 elems)  -> 80 B rows
#define PX 136                     // X smem pitch (bf16 elems)  -> 272 B rows
#define A_BYTES (128 * PA * 2)     // 10240
#define X_BYTES (32 * PX * 2)      // 8704
#define ST_A_HI 0
#define ST_A_LO (A_BYTES)
#define ST_X_HI (2 * A_BYTES)
#define ST_X_LO (2 * A_BYTES + X_BYTES)
#define STAGE_SZ (2 * A_BYTES + 2 * X_BYTES)   // 37888
#define SMEM_GEMM (2 * STAGE_SZ)               // 75776

__global__ __launch_bounds__(512, 1)
void gemm_mma(const float* __restrict__ x, float* __restrict__ out) {
    extern __shared__ __align__(16) char smem[];
    const uint32_t sb = smem_u32(smem);
    const int tid = threadIdx.x, lane = tid & 31, wid = tid >> 5;
    const int b = blockIdx.z, o0 = blockIdx.y * 128, l0 = blockIdx.x * 128;
    const int m0w = (wid & 3) * 32;    // warp m origin
    const int n0w = (wid >> 2) * 32;   // warp n origin

    const uint4* Ah = (const uint4*)g_bw_hi + ((size_t)(b * O_ + o0)) * (I_ / 8);
    const uint4* Al = (const uint4*)g_bw_lo + ((size_t)(b * O_ + o0)) * (I_ / 8);
    const float* xb = x + (size_t)b * I_ * L_;

    // global->smem load mappings
    const int aRow = tid >> 2, aC = tid & 3;          // A: 128 rows x 4 uint4
    const int xRow = tid >> 5;                         // X: rows 0..15 (+16 for r=1)
    const int xCol = (tid & 31) * 4;                   // 4 floats per thread per row

    float acc[2][4][4] = {};
    uint4 pa_h, pa_l;
    float4 px0, px1;

    // ldmatrix lane addressing
    const uint32_t frow = lane & 15, fc8 = (lane >> 4) * 8;

#define LDG_CHUNK(k0) do { \
        const int kq = (k0) >> 3; \
        pa_h = Ah[aRow * (I_ / 8) + kq + aC]; \
        pa_l = Al[aRow * (I_ / 8) + kq + aC]; \
        px0 = *(const float4*)&xb[(size_t)((k0) + xRow) * L_ + l0 + xCol]; \
        px1 = *(const float4*)&xb[(size_t)((k0) + xRow + 16) * L_ + l0 + xCol]; \
    } while (0)

#define CVT_STS_X(v, rowoff, base) do { \
        __nv_bfloat16 hx = __float2bfloat16((v).x), hy = __float2bfloat16((v).y); \
        __nv_bfloat16 hz = __float2bfloat16((v).z), hw = __float2bfloat16((v).w); \
        __nv_bfloat16 lx = __float2bfloat16((v).x - __bfloat162float(hx)); \
        __nv_bfloat16 ly = __float2bfloat16((v).y - __bfloat162float(hy)); \
        __nv_bfloat16 lz = __float2bfloat16((v).z - __bfloat162float(hz)); \
        __nv_bfloat16 lw = __float2bfloat16((v).w - __bfloat162float(hw)); \
        uint2 hv, lv; \
        hv.x = (uint32_t)__bfloat16_as_ushort(hx) | ((uint32_t)__bfloat16_as_ushort(hy) << 16); \
        hv.y = (uint32_t)__bfloat16_as_ushort(hz) | ((uint32_t)__bfloat16_as_ushort(hw) << 16); \
        lv.x = (uint32_t)__bfloat16_as_ushort(lx) | ((uint32_t)__bfloat16_as_ushort(ly) << 16); \
        lv.y = (uint32_t)__bfloat16_as_ushort(lz) | ((uint32_t)__bfloat16_as_ushort(lw) << 16); \
        *(uint2*)(smem + (base) + ST_X_HI + (rowoff) * (PX * 2) + xCol * 2) = hv; \
        *(uint2*)(smem + (base) + ST_X_LO + (rowoff) * (PX * 2) + xCol * 2) = lv; \
    } while (0)

#define STS_CHUNK(base) do { \
        *(uint4*)(smem + (base) + ST_A_HI + aRow * (PA * 2) + aC * 16) = pa_h; \
        *(uint4*)(smem + (base) + ST_A_LO + aRow * (PA * 2) + aC * 16) = pa_l; \
        CVT_STS_X(px0, xRow, base); \
        CVT_STS_X(px1, xRow + 16, base); \
    } while (0)

    // prologue
    LDG_CHUNK(0);
    STS_CHUNK(0);
    __syncthreads();

    for (int c = 0; c < I_ / 32; c++) {
        const uint32_t cur = (c & 1) * STAGE_SZ;
        if (c < I_ / 32 - 1) LDG_CHUNK((c + 1) * 32);

        #pragma unroll
        for (int ks = 0; ks < 2; ks++) {
            uint32_t ah[2][4], al[2][4], bh[2][4], bl[2][4];
            #pragma unroll
            for (int mi = 0; mi < 2; mi++) {
                const uint32_t ad = sb + cur + ST_A_HI
                    + (m0w + mi * 16 + frow) * (PA * 2) + (ks * 16 + fc8) * 2;
                LDSM4(ah[mi], ad);
                LDSM4(al[mi], ad + A_BYTES);
            }
            #pragma unroll
            for (int np = 0; np < 2; np++) {
                const uint32_t bd = sb + cur + ST_X_HI
                    + (ks * 16 + frow) * (PX * 2) + (n0w + np * 16 + fc8) * 2;
                LDSM4T(bh[np], bd);
                LDSM4T(bl[np], bd + X_BYTES);
            }
            #pragma unroll
            for (int mi = 0; mi < 2; mi++) {
                #pragma unroll
                for (int nt = 0; nt < 4; nt++) {
                    const int np = nt >> 1, hp = (nt & 1) * 2;
                    MMA_BF16(acc[mi][nt], ah[mi], bh[np][hp], bh[np][hp + 1]);
                    MMA_BF16(acc[mi][nt], ah[mi], bl[np][hp], bl[np][hp + 1]);
                    MMA_BF16(acc[mi][nt], al[mi], bh[np][hp], bh[np][hp + 1]);
                }
            }
        }

        if (c < I_ / 32 - 1) {
            STS_CHUNK((1 - (c & 1)) * STAGE_SZ);
        }
        __syncthreads();
    }

    // epilogue
    const int g = lane >> 2, c2 = (lane & 3) * 2;
    #pragma unroll
    for (int mi = 0; mi < 2; mi++) {
        #pragma unroll
        for (int nt = 0; nt < 4; nt++) {
            const int o = o0 + m0w + mi * 16 + g;
            const int l = l0 + n0w + nt * 8 + c2;
            float* p = out + ((size_t)(b * O_ + o)) * L_ + l;
            float2 v0 = {acc[mi][nt][0], acc[mi][nt][1]};
            float2 v1 = {acc[mi][nt][2], acc[mi][nt][3]};
            *(float2*)p = v0;
            *(float2*)(p + 8 * L_) = v1;
        }
    }
#undef LDG_CHUNK
#undef CVT_STS_X
#undef STS_CHUNK
}

// ---------------------------------------------------------------------------
extern "C" void kernel_launch(void* const* d_in, const int* in_sizes, int n_in,
                              void* d_out, int out_size) {
    const float* x      = (const float*)d_in[0];
    const float* t      = (const float*)d_in[1];
    const float* weight = (const float*)d_in[2];
    const float* W1     = (const float*)d_in[3];
    const float* b1     = (const float*)d_in[4];
    const float* W2     = (const float*)d_in[5];
    const float* b2     = (const float*)d_in[6];
    const float* W3     = (const float*)d_in[7];
    const float* b3     = (const float*)d_in[8];
    float* out = (float*)d_out;

    cudaFuncSetAttribute(gemm_mma, cudaFuncAttributeMaxDynamicSharedMemorySize, SMEM_GEMM);

    mlp_kernel<<<B_, 256>>>(t, W1, b1, W2, b2, W3, b3);
    demod_kernel<<<dim3(O_, B_), 128>>>(weight);
    gemm_mma<<<dim3(L_ / 128, O_ / 128, B_), 512, SMEM_GEMM>>>(x, out);
}

// round 5
// speedup vs baseline: 2.2890x; 1.0734x over previous
#include <cuda_runtime.h>
#include <cuda_bf16.h>
#include <cstdint>
#include <math.h>

#define B_ 16
#define I_ 512
#define O_ 512
#define T_ 256
#define L_ 4096
#define EPS_ 1e-8f

// ---------------------------------------------------------------------------
// Scratch
// ---------------------------------------------------------------------------
__device__ float g_s[B_ * I_];
__device__ float g_h1[B_ * T_];
__device__ float g_h2[B_ * T_];
__device__ __nv_bfloat16 g_bw_hi[B_ * O_ * I_];      // 8 MB
__device__ __nv_bfloat16 g_bw_lo[B_ * O_ * I_];      // 8 MB

// ---------------------------------------------------------------------------
// Helpers
// ---------------------------------------------------------------------------
__device__ __forceinline__ uint32_t smem_u32(const void* p) {
    uint32_t a;
    asm("{ .reg .u64 t; cvta.to.shared.u64 t, %1; cvt.u32.u64 %0, t; }" : "=r"(a) : "l"(p));
    return a;
}

#define LDSM4(r, addr) \
    asm volatile("ldmatrix.sync.aligned.m8n8.x4.shared.b16 {%0,%1,%2,%3}, [%4];" \
        : "=r"((r)[0]), "=r"((r)[1]), "=r"((r)[2]), "=r"((r)[3]) : "r"(addr))

#define LDSM4T(r, addr) \
    asm volatile("ldmatrix.sync.aligned.m8n8.x4.trans.shared.b16 {%0,%1,%2,%3}, [%4];" \
        : "=r"((r)[0]), "=r"((r)[1]), "=r"((r)[2]), "=r"((r)[3]) : "r"(addr))

#define MMA_BF16(acc, a, b0, b1) \
    asm volatile("mma.sync.aligned.m16n8k16.row.col.f32.bf16.bf16.f32 " \
        "{%0,%1,%2,%3}, {%4,%5,%6,%7}, {%8,%9}, {%0,%1,%2,%3};" \
        : "+f"((acc)[0]), "+f"((acc)[1]), "+f"((acc)[2]), "+f"((acc)[3]) \
        : "r"((a)[0]), "r"((a)[1]), "r"((a)[2]), "r"((a)[3]), "r"(b0), "r"(b1))

#define CP_ASYNC16(smem_addr, gptr) \
    asm volatile("cp.async.cg.shared.global [%0], [%1], 16;" :: "r"(smem_addr), "l"(gptr))
#define CP_ASYNC_COMMIT() asm volatile("cp.async.commit_group;" ::: "memory")
#define CP_ASYNC_WAIT0()  asm volatile("cp.async.wait_group 0;" ::: "memory")

// ---------------------------------------------------------------------------
// Kernel 1: one linear layer, one warp per output. grid = (out_dim/8, B).
// out[b, j] = act( sum_k in[b,k] * W[j,k] + bias[j] + add_const )
// ---------------------------------------------------------------------------
__global__ void lin_kernel(const float* __restrict__ in, const float* __restrict__ W,
                           const float* __restrict__ bias, float* __restrict__ out,
                           int out_dim, int do_silu, float add_const) {
    const int b = blockIdx.y;
    const int wid = threadIdx.x >> 5, lid = threadIdx.x & 31;
    const int j = blockIdx.x * 8 + wid;

    const float* inv = in + b * T_;
    const float* wrow = W + j * T_;
    float acc = 0.0f;
    #pragma unroll
    for (int u = 0; u < T_ / 32; u++)
        acc += inv[lid + u * 32] * wrow[lid + u * 32];
    #pragma unroll
    for (int off = 16; off > 0; off >>= 1) acc += __shfl_xor_sync(0xFFFFFFFFu, acc, off);
    if (lid == 0) {
        float z = acc + bias[j] + add_const;
        out[b * out_dim + j] = do_silu ? z / (1.0f + expf(-z)) : z;
    }
}

// ---------------------------------------------------------------------------
// Kernel 2: demodulation -> bf16 hi/lo weights, K-major [b][o][i].
// ---------------------------------------------------------------------------
__global__ void demod_kernel(const float* __restrict__ weight) {
    const int o = blockIdx.x, b = blockIdx.y;
    const int tid = threadIdx.x;  // 0..127
    const float* srow = g_s + b * I_;
    const float* wrow = weight + o * I_;

    float v[4];
    float ss = 0.0f;
    #pragma unroll
    for (int r = 0; r < 4; r++) {
        const int i = tid + r * 128;
        const float val = wrow[i] * srow[i];
        v[r] = val;
        ss += val * val;
    }
    #pragma unroll
    for (int off = 16; off > 0; off >>= 1) ss += __shfl_xor_sync(0xFFFFFFFFu, ss, off);
    __shared__ float red[4];
    if ((tid & 31) == 0) red[tid >> 5] = ss;
    __syncthreads();
    const float d = rsqrtf(red[0] + red[1] + red[2] + red[3] + EPS_);

    const size_t base = ((size_t)b * O_ + o) * I_;
    #pragma unroll
    for (int r = 0; r < 4; r++) {
        const float val = v[r] * d;
        const __nv_bfloat16 hi = __float2bfloat16(val);
        const __nv_bfloat16 lo = __float2bfloat16(val - __bfloat162float(hi));
        g_bw_hi[base + tid + r * 128] = hi;
        g_bw_lo[base + tid + r * 128] = lo;
    }
}

// ---------------------------------------------------------------------------
// Kernel 3: mma.sync batched GEMM  out[b,o,l] = sum_i bw[b,o,i] * x[b,i,l]
// Block tile 128(M) x 128(N), K chunks of 32, 256 threads (8 warps),
// warp tile 64x32 (2M x 4N warp grid). bf16 hi/lo 3-MMA split, fp32 accum.
// A tiles via cp.async (bf16 in gmem); X converted fp32->bf16 hi/lo in RF.
// ---------------------------------------------------------------------------
#define PA 40                      // A smem pitch (bf16)  -> 80 B rows
#define PX 136                     // X smem pitch (bf16)  -> 272 B rows
#define A_BYTES (128 * PA * 2)     // 10240
#define X_BYTES (32 * PX * 2)      // 8704
#define ST_A_HI 0
#define ST_A_LO (A_BYTES)
#define ST_X_HI (2 * A_BYTES)
#define ST_X_LO (2 * A_BYTES + X_BYTES)
#define STAGE_SZ (2 * A_BYTES + 2 * X_BYTES)   // 37888
#define SMEM_GEMM (2 * STAGE_SZ)               // 75776

__global__ __launch_bounds__(256, 1)
void gemm_mma(const float* __restrict__ x, float* __restrict__ out) {
    extern __shared__ __align__(16) char smem[];
    const uint32_t sb = smem_u32(smem);
    const int tid = threadIdx.x, lane = tid & 31, wid = tid >> 5;
    const int b = blockIdx.z, o0 = blockIdx.y * 128, l0 = blockIdx.x * 128;
    const int m0w = (wid & 1) * 64;    // warp m origin (2 warps in M)
    const int n0w = (wid >> 1) * 32;   // warp n origin (4 warps in N)

    const __nv_bfloat16* AhG = g_bw_hi + ((size_t)(b * O_ + o0)) * I_;
    const __nv_bfloat16* AlG = g_bw_lo + ((size_t)(b * O_ + o0)) * I_;
    const float* xb = x + (size_t)b * I_ * L_;

    // A: 128 rows x 4 uint4 per buffer; 2 passes per thread
    const int aRow0 = tid >> 2, aC = tid & 3;             // pass r: row = aRow0 + 64*r
    // X: 32 rows x 32 float4; 4 passes per thread
    const int xRow0 = tid >> 5;                            // pass r: row = xRow0 + 8*r
    const int xCol = (tid & 31) * 4;

    float acc[4][4][4] = {};
    float4 px[4];

    const uint32_t frow = lane & 15, fc8 = (lane >> 4) * 8;

#define CP_A(k0, base) do { \
        const int koff = (k0); \
        _Pragma("unroll") \
        for (int r = 0; r < 2; r++) { \
            const int row = aRow0 + 64 * r; \
            const uint32_t d = sb + (base) + row * (PA * 2) + aC * 16; \
            CP_ASYNC16(d + ST_A_HI, (const char*)(AhG + (size_t)row * I_ + koff + aC * 8)); \
            CP_ASYNC16(d + ST_A_LO, (const char*)(AlG + (size_t)row * I_ + koff + aC * 8)); \
        } \
        CP_ASYNC_COMMIT(); \
    } while (0)

#define LDG_X(k0) do { \
        _Pragma("unroll") \
        for (int r = 0; r < 4; r++) \
            px[r] = *(const float4*)&xb[(size_t)((k0) + xRow0 + 8 * r) * L_ + l0 + xCol]; \
    } while (0)

#define STS_X(base) do { \
        _Pragma("unroll") \
        for (int r = 0; r < 4; r++) { \
            const int row = xRow0 + 8 * r; \
            __nv_bfloat16 hx = __float2bfloat16(px[r].x), hy = __float2bfloat16(px[r].y); \
            __nv_bfloat16 hz = __float2bfloat16(px[r].z), hw = __float2bfloat16(px[r].w); \
            __nv_bfloat16 lx = __float2bfloat16(px[r].x - __bfloat162float(hx)); \
            __nv_bfloat16 ly = __float2bfloat16(px[r].y - __bfloat162float(hy)); \
            __nv_bfloat16 lz = __float2bfloat16(px[r].z - __bfloat162float(hz)); \
            __nv_bfloat16 lw = __float2bfloat16(px[r].w - __bfloat162float(hw)); \
            uint2 hv, lv; \
            hv.x = (uint32_t)__bfloat16_as_ushort(hx) | ((uint32_t)__bfloat16_as_ushort(hy) << 16); \
            hv.y = (uint32_t)__bfloat16_as_ushort(hz) | ((uint32_t)__bfloat16_as_ushort(hw) << 16); \
            lv.x = (uint32_t)__bfloat16_as_ushort(lx) | ((uint32_t)__bfloat16_as_ushort(ly) << 16); \
            lv.y = (uint32_t)__bfloat16_as_ushort(lz) | ((uint32_t)__bfloat16_as_ushort(lw) << 16); \
            *(uint2*)(smem + (base) + ST_X_HI + row * (PX * 2) + xCol * 2) = hv; \
            *(uint2*)(smem + (base) + ST_X_LO + row * (PX * 2) + xCol * 2) = lv; \
        } \
    } while (0)

    // prologue: chunk 0 into stage 0
    LDG_X(0);
    CP_A(0, 0);
    STS_X(0);
    CP_ASYNC_WAIT0();
    __syncthreads();

    #pragma unroll 1
    for (int c = 0; c < I_ / 32; c++) {
        const uint32_t cur = (uint32_t)(c & 1) * STAGE_SZ;
        const uint32_t nxt = (uint32_t)(1 - (c & 1)) * STAGE_SZ;
        const bool has_next = (c < I_ / 32 - 1);

        if (has_next) {
            CP_A((c + 1) * 32, nxt);   // async, overlaps compute below
            LDG_X((c + 1) * 32);
        }

        #pragma unroll
        for (int ks = 0; ks < 2; ks++) {
            uint32_t ah[4][4], al[4][4], bh[2][4], bl[2][4];
            #pragma unroll
            for (int mi = 0; mi < 4; mi++) {
                const uint32_t ad = sb + cur + ST_A_HI
                    + (m0w + mi * 16 + frow) * (PA * 2) + (ks * 16 + fc8) * 2;
                LDSM4(ah[mi], ad);
                LDSM4(al[mi], ad + A_BYTES);
            }
            #pragma unroll
            for (int np = 0; np < 2; np++) {
                const uint32_t bd = sb + cur + ST_X_HI
                    + (ks * 16 + frow) * (PX * 2) + (n0w + np * 16 + fc8) * 2;
                LDSM4T(bh[np], bd);
                LDSM4T(bl[np], bd + X_BYTES);
            }
            #pragma unroll
            for (int mi = 0; mi < 4; mi++) {
                #pragma unroll
                for (int nt = 0; nt < 4; nt++) {
                    const int np = nt >> 1, hp = (nt & 1) * 2;
                    MMA_BF16(acc[mi][nt], ah[mi], bh[np][hp], bh[np][hp + 1]);
                    MMA_BF16(acc[mi][nt], ah[mi], bl[np][hp], bl[np][hp + 1]);
                    MMA_BF16(acc[mi][nt], al[mi], bh[np][hp], bh[np][hp + 1]);
                }
            }
        }

        if (has_next) STS_X(nxt);
        CP_ASYNC_WAIT0();
        __syncthreads();
    }

    // epilogue
    const int g = lane >> 2, c2 = (lane & 3) * 2;
    #pragma unroll
    for (int mi = 0; mi < 4; mi++) {
        #pragma unroll
        for (int nt = 0; nt < 4; nt++) {
            const int o = o0 + m0w + mi * 16 + g;
            const int l = l0 + n0w + nt * 8 + c2;
            float* p = out + ((size_t)(b * O_ + o)) * L_ + l;
            float2 v0 = {acc[mi][nt][0], acc[mi][nt][1]};
            float2 v1 = {acc[mi][nt][2], acc[mi][nt][3]};
            *(float2*)p = v0;
            *(float2*)(p + 8 * L_) = v1;
        }
    }
#undef CP_A
#undef LDG_X
#undef STS_X
}

// ---------------------------------------------------------------------------
extern "C" void kernel_launch(void* const* d_in, const int* in_sizes, int n_in,
                              void* d_out, int out_size) {
    const float* x      = (const float*)d_in[0];
    const float* t      = (const float*)d_in[1];
    const float* weight = (const float*)d_in[2];
    const float* W1     = (const float*)d_in[3];
    const float* b1     = (const float*)d_in[4];
    const float* W2     = (const float*)d_in[5];
    const float* b2     = (const float*)d_in[6];
    const float* W3     = (const float*)d_in[7];
    const float* b3     = (const float*)d_in[8];
    float* out = (float*)d_out;

    cudaFuncSetAttribute(gemm_mma, cudaFuncAttributeMaxDynamicSharedMemorySize, SMEM_GEMM);

    float* h1 = nullptr; float* h2 = nullptr; float* s = nullptr;
    cudaGetSymbolAddress((void**)&h1, g_h1);
    cudaGetSymbolAddress((void**)&h2, g_h2);
    cudaGetSymbolAddress((void**)&s,  g_s);

    lin_kernel<<<dim3(T_ / 8, B_), 256>>>(t,  W1, b1, h1, T_, 1, 0.0f);
    lin_kernel<<<dim3(T_ / 8, B_), 256>>>(h1, W2, b2, h2, T_, 1, 0.0f);
    lin_kernel<<<dim3(I_ / 8, B_), 256>>>(h2, W3, b3, s,  I_, 0, 1.0f);
    demod_kernel<<<dim3(O_, B_), 128>>>(weight);
    gemm_mma<<<dim3(L_ / 128, O_ / 128, B_), 256, SMEM_GEMM>>>(x, out);
}

// round 6
// speedup vs baseline: 2.8958x; 1.2651x over previous
#include <cuda_runtime.h>
#include <cuda_fp16.h>
#include <cstdint>
#include <math.h>

#define B_ 16
#define I_ 512
#define O_ 512
#define T_ 256
#define L_ 4096
#define EPS_ 1e-8f

// ---------------------------------------------------------------------------
// Scratch
// ---------------------------------------------------------------------------
__device__ float g_s[B_ * I_];
__device__ float g_h1[B_ * T_];
__device__ float g_h2[B_ * T_];
__device__ __half g_bw_hi[B_ * O_ * I_];      // 8 MB
__device__ __half g_bw_lo[B_ * O_ * I_];      // 8 MB

// ---------------------------------------------------------------------------
// Helpers
// ---------------------------------------------------------------------------
__device__ __forceinline__ uint32_t smem_u32(const void* p) {
    uint32_t a;
    asm("{ .reg .u64 t; cvta.to.shared.u64 t, %1; cvt.u32.u64 %0, t; }" : "=r"(a) : "l"(p));
    return a;
}

#define LDSM4(r, addr) \
    asm volatile("ldmatrix.sync.aligned.m8n8.x4.shared.b16 {%0,%1,%2,%3}, [%4];" \
        : "=r"((r)[0]), "=r"((r)[1]), "=r"((r)[2]), "=r"((r)[3]) : "r"(addr))

#define LDSM4T(r, addr) \
    asm volatile("ldmatrix.sync.aligned.m8n8.x4.trans.shared.b16 {%0,%1,%2,%3}, [%4];" \
        : "=r"((r)[0]), "=r"((r)[1]), "=r"((r)[2]), "=r"((r)[3]) : "r"(addr))

#define MMA_F16(acc, a, b0, b1) \
    asm volatile("mma.sync.aligned.m16n8k16.row.col.f32.f16.f16.f32 " \
        "{%0,%1,%2,%3}, {%4,%5,%6,%7}, {%8,%9}, {%0,%1,%2,%3};" \
        : "+f"((acc)[0]), "+f"((acc)[1]), "+f"((acc)[2]), "+f"((acc)[3]) \
        : "r"((a)[0]), "r"((a)[1]), "r"((a)[2]), "r"((a)[3]), "r"(b0), "r"(b1))

#define CP_ASYNC16(smem_addr, gptr) \
    asm volatile("cp.async.cg.shared.global [%0], [%1], 16;" :: "r"(smem_addr), "l"(gptr))
#define CP_ASYNC_COMMIT() asm volatile("cp.async.commit_group;" ::: "memory")
#define CP_ASYNC_WAIT0()  asm volatile("cp.async.wait_group 0;" ::: "memory")

// ---------------------------------------------------------------------------
// Kernel 1: one linear layer, one warp per output. grid = (out_dim/8, B).
// ---------------------------------------------------------------------------
__global__ void lin_kernel(const float* __restrict__ in, const float* __restrict__ W,
                           const float* __restrict__ bias, float* __restrict__ out,
                           int out_dim, int do_silu, float add_const) {
    const int b = blockIdx.y;
    const int wid = threadIdx.x >> 5, lid = threadIdx.x & 31;
    const int j = blockIdx.x * 8 + wid;

    const float* inv = in + b * T_;
    const float* wrow = W + j * T_;
    float acc = 0.0f;
    #pragma unroll
    for (int u = 0; u < T_ / 32; u++)
        acc += inv[lid + u * 32] * wrow[lid + u * 32];
    #pragma unroll
    for (int off = 16; off > 0; off >>= 1) acc += __shfl_xor_sync(0xFFFFFFFFu, acc, off);
    if (lid == 0) {
        float z = acc + bias[j] + add_const;
        out[b * out_dim + j] = do_silu ? z / (1.0f + expf(-z)) : z;
    }
}

// ---------------------------------------------------------------------------
// Kernel 2: demodulation -> fp16 hi/lo weights, K-major [b][o][i].
// ---------------------------------------------------------------------------
__global__ void demod_kernel(const float* __restrict__ weight) {
    const int o = blockIdx.x, b = blockIdx.y;
    const int tid = threadIdx.x;  // 0..127
    const float* srow = g_s + b * I_;
    const float* wrow = weight + o * I_;

    float v[4];
    float ss = 0.0f;
    #pragma unroll
    for (int r = 0; r < 4; r++) {
        const int i = tid + r * 128;
        const float val = wrow[i] * srow[i];
        v[r] = val;
        ss += val * val;
    }
    #pragma unroll
    for (int off = 16; off > 0; off >>= 1) ss += __shfl_xor_sync(0xFFFFFFFFu, ss, off);
    __shared__ float red[4];
    if ((tid & 31) == 0) red[tid >> 5] = ss;
    __syncthreads();
    const float d = rsqrtf(red[0] + red[1] + red[2] + red[3] + EPS_);

    const size_t base = ((size_t)b * O_ + o) * I_;
    #pragma unroll
    for (int r = 0; r < 4; r++) {
        const float val = v[r] * d;
        const __half hi = __float2half_rn(val);
        const __half lo = __float2half_rn(val - __half2float(hi));
        g_bw_hi[base + tid + r * 128] = hi;
        g_bw_lo[base + tid + r * 128] = lo;
    }
}

// ---------------------------------------------------------------------------
// Kernel 3: mma.sync fp16 batched GEMM  out[b,o,l] = sum_i bw[b,o,i]*x[b,i,l]
// Block tile 128(M) x 128(N), K chunks of 32, 256 threads (8 warps),
// warp tile 64x32. A split hi/lo (2-MMA), x single fp16, fp32 accum.
// A tiles via cp.async; x converted fp32->fp16 in RF during staging.
// ---------------------------------------------------------------------------
#define PA 40                      // A smem pitch (fp16)  -> 80 B rows
#define PX 136                     // X smem pitch (fp16)  -> 272 B rows
#define A_BYTES (128 * PA * 2)     // 10240
#define X_BYTES (32 * PX * 2)      // 8704
#define ST_A_HI 0
#define ST_A_LO (A_BYTES)
#define ST_X    (2 * A_BYTES)
#define STAGE_SZ (2 * A_BYTES + X_BYTES)       // 29184
#define SMEM_GEMM (2 * STAGE_SZ)               // 58368

__global__ __launch_bounds__(256, 1)
void gemm_mma(const float* __restrict__ x, float* __restrict__ out) {
    extern __shared__ __align__(16) char smem[];
    const uint32_t sb = smem_u32(smem);
    const int tid = threadIdx.x, lane = tid & 31, wid = tid >> 5;
    const int b = blockIdx.z, o0 = blockIdx.y * 128, l0 = blockIdx.x * 128;
    const int m0w = (wid & 1) * 64;    // warp m origin (2 warps in M)
    const int n0w = (wid >> 1) * 32;   // warp n origin (4 warps in N)

    const __half* AhG = g_bw_hi + ((size_t)(b * O_ + o0)) * I_;
    const __half* AlG = g_bw_lo + ((size_t)(b * O_ + o0)) * I_;
    const float* xb = x + (size_t)b * I_ * L_;

    const int aRow0 = tid >> 2, aC = tid & 3;     // A: pass r -> row aRow0 + 64*r
    const int xRow0 = tid >> 5;                   // X: pass r -> row xRow0 + 8*r
    const int xCol = (tid & 31) * 4;

    float acc[4][4][4] = {};
    float4 px[4];

    const uint32_t frow = lane & 15, fc8 = (lane >> 4) * 8;

#define CP_A(k0, base) do { \
        const int koff = (k0); \
        _Pragma("unroll") \
        for (int r = 0; r < 2; r++) { \
            const int row = aRow0 + 64 * r; \
            const uint32_t d = sb + (base) + row * (PA * 2) + aC * 16; \
            CP_ASYNC16(d + ST_A_HI, (const char*)(AhG + (size_t)row * I_ + koff + aC * 8)); \
            CP_ASYNC16(d + ST_A_LO, (const char*)(AlG + (size_t)row * I_ + koff + aC * 8)); \
        } \
        CP_ASYNC_COMMIT(); \
    } while (0)

#define LDG_X(k0) do { \
        _Pragma("unroll") \
        for (int r = 0; r < 4; r++) \
            px[r] = *(const float4*)&xb[(size_t)((k0) + xRow0 + 8 * r) * L_ + l0 + xCol]; \
    } while (0)

#define STS_X(base) do { \
        _Pragma("unroll") \
        for (int r = 0; r < 4; r++) { \
            const int row = xRow0 + 8 * r; \
            const __half hx = __float2half_rn(px[r].x), hy = __float2half_rn(px[r].y); \
            const __half hz = __float2half_rn(px[r].z), hw = __float2half_rn(px[r].w); \
            uint2 hv; \
            hv.x = (uint32_t)__half_as_ushort(hx) | ((uint32_t)__half_as_ushort(hy) << 16); \
            hv.y = (uint32_t)__half_as_ushort(hz) | ((uint32_t)__half_as_ushort(hw) << 16); \
            *(uint2*)(smem + (base) + ST_X + row * (PX * 2) + xCol * 2) = hv; \
        } \
    } while (0)

    // prologue: chunk 0 into stage 0
    LDG_X(0);
    CP_A(0, 0);
    STS_X(0);
    CP_ASYNC_WAIT0();
    __syncthreads();

    #pragma unroll 1
    for (int c = 0; c < I_ / 32; c++) {
        const uint32_t cur = (uint32_t)(c & 1) * STAGE_SZ;
        const uint32_t nxt = (uint32_t)(1 - (c & 1)) * STAGE_SZ;
        const bool has_next = (c < I_ / 32 - 1);

        if (has_next) {
            CP_A((c + 1) * 32, nxt);   // async, overlaps compute below
            LDG_X((c + 1) * 32);
        }

        #pragma unroll
        for (int ks = 0; ks < 2; ks++) {
            uint32_t ah[4][4], al[4][4], bh[2][4];
            #pragma unroll
            for (int mi = 0; mi < 4; mi++) {
                const uint32_t ad = sb + cur + ST_A_HI
                    + (m0w + mi * 16 + frow) * (PA * 2) + (ks * 16 + fc8) * 2;
                LDSM4(ah[mi], ad);
                LDSM4(al[mi], ad + A_BYTES);
            }
            #pragma unroll
            for (int np = 0; np < 2; np++) {
                const uint32_t bd = sb + cur + ST_X
                    + (ks * 16 + frow) * (PX * 2) + (n0w + np * 16 + fc8) * 2;
                LDSM4T(bh[np], bd);
            }
            #pragma unroll
            for (int mi = 0; mi < 4; mi++) {
                #pragma unroll
                for (int nt = 0; nt < 4; nt++) {
                    const int np = nt >> 1, hp = (nt & 1) * 2;
                    MMA_F16(acc[mi][nt], ah[mi], bh[np][hp], bh[np][hp + 1]);
                    MMA_F16(acc[mi][nt], al[mi], bh[np][hp], bh[np][hp + 1]);
                }
            }
        }

        if (has_next) STS_X(nxt);
        CP_ASYNC_WAIT0();
        __syncthreads();
    }

    // epilogue
    const int g = lane >> 2, c2 = (lane & 3) * 2;
    #pragma unroll
    for (int mi = 0; mi < 4; mi++) {
        #pragma unroll
        for (int nt = 0; nt < 4; nt++) {
            const int o = o0 + m0w + mi * 16 + g;
            const int l = l0 + n0w + nt * 8 + c2;
            float* p = out + ((size_t)(b * O_ + o)) * L_ + l;
            float2 v0 = {acc[mi][nt][0], acc[mi][nt][1]};
            float2 v1 = {acc[mi][nt][2], acc[mi][nt][3]};
            *(float2*)p = v0;
            *(float2*)(p + 8 * L_) = v1;
        }
    }
#undef CP_A
#undef LDG_X
#undef STS_X
}

// ---------------------------------------------------------------------------
extern "C" void kernel_launch(void* const* d_in, const int* in_sizes, int n_in,
                              void* d_out, int out_size) {
    const float* x      = (const float*)d_in[0];
    const float* t      = (const float*)d_in[1];
    const float* weight = (const float*)d_in[2];
    const float* W1     = (const float*)d_in[3];
    const float* b1     = (const float*)d_in[4];
    const float* W2     = (const float*)d_in[5];
    const float* b2     = (const float*)d_in[6];
    const float* W3     = (const float*)d_in[7];
    const float* b3     = (const float*)d_in[8];
    float* out = (float*)d_out;

    cudaFuncSetAttribute(gemm_mma, cudaFuncAttributeMaxDynamicSharedMemorySize, SMEM_GEMM);

    float* h1 = nullptr; float* h2 = nullptr; float* s = nullptr;
    cudaGetSymbolAddress((void**)&h1, g_h1);
    cudaGetSymbolAddress((void**)&h2, g_h2);
    cudaGetSymbolAddress((void**)&s,  g_s);

    lin_kernel<<<dim3(T_ / 8, B_), 256>>>(t,  W1, b1, h1, T_, 1, 0.0f);
    lin_kernel<<<dim3(T_ / 8, B_), 256>>>(h1, W2, b2, h2, T_, 1, 0.0f);
    lin_kernel<<<dim3(I_ / 8, B_), 256>>>(h2, W3, b3, s,  I_, 0, 1.0f);
    demod_kernel<<<dim3(O_, B_), 128>>>(weight);
    gemm_mma<<<dim3(L_ / 128, O_ / 128, B_), 256, SMEM_GEMM>>>(x, out);
}

// round 7
// speedup vs baseline: 5.4664x; 1.8877x over previous
#include <cuda_runtime.h>
#include <cuda_fp16.h>
#include <cstdint>
#include <math.h>

#define B_ 16
#define I_ 512
#define O_ 512
#define T_ 256
#define L_ 4096
#define EPS_ 1e-8f

// ---------------------------------------------------------------------------
// Scratch
// ---------------------------------------------------------------------------
__device__ float g_s[B_ * I_];
__device__ float g_h1[B_ * T_];
__device__ float g_h2[B_ * T_];
__device__ __half g_bw[B_ * O_ * I_];      // 8 MB, demodulated weights fp16

// ---------------------------------------------------------------------------
// Helpers
// ---------------------------------------------------------------------------
__device__ __forceinline__ uint32_t smem_u32(const void* p) {
    uint32_t a;
    asm("{ .reg .u64 t; cvta.to.shared.u64 t, %1; cvt.u32.u64 %0, t; }" : "=r"(a) : "l"(p));
    return a;
}

#define LDSM4(r, addr) \
    asm volatile("ldmatrix.sync.aligned.m8n8.x4.shared.b16 {%0,%1,%2,%3}, [%4];" \
        : "=r"((r)[0]), "=r"((r)[1]), "=r"((r)[2]), "=r"((r)[3]) : "r"(addr))

#define LDSM4T(r, addr) \
    asm volatile("ldmatrix.sync.aligned.m8n8.x4.trans.shared.b16 {%0,%1,%2,%3}, [%4];" \
        : "=r"((r)[0]), "=r"((r)[1]), "=r"((r)[2]), "=r"((r)[3]) : "r"(addr))

#define MMA_F16(acc, a, b0, b1) \
    asm volatile("mma.sync.aligned.m16n8k16.row.col.f32.f16.f16.f32 " \
        "{%0,%1,%2,%3}, {%4,%5,%6,%7}, {%8,%9}, {%0,%1,%2,%3};" \
        : "+f"((acc)[0]), "+f"((acc)[1]), "+f"((acc)[2]), "+f"((acc)[3]) \
        : "r"((a)[0]), "r"((a)[1]), "r"((a)[2]), "r"((a)[3]), "r"(b0), "r"(b1))

#define CP_ASYNC16(smem_addr, gptr) \
    asm volatile("cp.async.cg.shared.global [%0], [%1], 16;" :: "r"(smem_addr), "l"(gptr))
#define CP_ASYNC_COMMIT() asm volatile("cp.async.commit_group;" ::: "memory")
#define CP_ASYNC_WAIT0()  asm volatile("cp.async.wait_group 0;" ::: "memory")

// ---------------------------------------------------------------------------
// Kernel 1: one linear layer, one warp per output. grid = (out_dim/8, B).
// ---------------------------------------------------------------------------
__global__ void lin_kernel(const float* __restrict__ in, const float* __restrict__ W,
                           const float* __restrict__ bias, float* __restrict__ out,
                           int out_dim, int do_silu, float add_const) {
    const int b = blockIdx.y;
    const int wid = threadIdx.x >> 5, lid = threadIdx.x & 31;
    const int j = blockIdx.x * 8 + wid;

    const float* inv = in + b * T_;
    const float* wrow = W + j * T_;
    float acc = 0.0f;
    #pragma unroll
    for (int u = 0; u < T_ / 32; u++)
        acc += inv[lid + u * 32] * wrow[lid + u * 32];
    #pragma unroll
    for (int off = 16; off > 0; off >>= 1) acc += __shfl_xor_sync(0xFFFFFFFFu, acc, off);
    if (lid == 0) {
        float z = acc + bias[j] + add_const;
        out[b * out_dim + j] = do_silu ? z / (1.0f + expf(-z)) : z;
    }
}

// ---------------------------------------------------------------------------
// Kernel 2: demodulation -> fp16 weights, K-major [b][o][i].
// ---------------------------------------------------------------------------
__global__ void demod_kernel(const float* __restrict__ weight) {
    const int o = blockIdx.x, b = blockIdx.y;
    const int tid = threadIdx.x;  // 0..127
    const float* srow = g_s + b * I_;
    const float* wrow = weight + o * I_;

    float v[4];
    float ss = 0.0f;
    #pragma unroll
    for (int r = 0; r < 4; r++) {
        const int i = tid + r * 128;
        const float val = wrow[i] * srow[i];
        v[r] = val;
        ss += val * val;
    }
    #pragma unroll
    for (int off = 16; off > 0; off >>= 1) ss += __shfl_xor_sync(0xFFFFFFFFu, ss, off);
    __shared__ float red[4];
    if ((tid & 31) == 0) red[tid >> 5] = ss;
    __syncthreads();
    const float d = rsqrtf(red[0] + red[1] + red[2] + red[3] + EPS_);

    const size_t base = ((size_t)b * O_ + o) * I_;
    #pragma unroll
    for (int r = 0; r < 4; r++)
        g_bw[base + tid + r * 128] = __float2half_rn(v[r] * d);
}

// ---------------------------------------------------------------------------
// Kernel 3: mma.sync fp16 batched GEMM  out[b,o,l] = sum_i bw[b,o,i]*x[b,i,l]
// Block tile 128(M) x 128(N), K chunks of 32, 256 threads (8 warps),
// warp tile 64x32, single fp16 A (1 MMA/tile-step), fp32 accum.
// A via cp.async; x converted fp32->fp16 in RF during staging. 2 CTAs/SM.
// ---------------------------------------------------------------------------
#define PA 40                      // A smem pitch (fp16)  -> 80 B rows
#define PX 136                     // X smem pitch (fp16)  -> 272 B rows
#define A_BYTES (128 * PA * 2)     // 10240
#define X_BYTES (32 * PX * 2)      // 8704
#define ST_A 0
#define ST_X (A_BYTES)
#define STAGE_SZ (A_BYTES + X_BYTES)           // 18944
#define SMEM_GEMM (2 * STAGE_SZ)               // 37888

__global__ __launch_bounds__(256, 2)
void gemm_mma(const float* __restrict__ x, float* __restrict__ out) {
    extern __shared__ __align__(16) char smem[];
    const uint32_t sb = smem_u32(smem);
    const int tid = threadIdx.x, lane = tid & 31, wid = tid >> 5;
    const int b = blockIdx.z, o0 = blockIdx.y * 128, l0 = blockIdx.x * 128;
    const int m0w = (wid & 1) * 64;    // warp m origin (2 warps in M)
    const int n0w = (wid >> 1) * 32;   // warp n origin (4 warps in N)

    const __half* AG = g_bw + ((size_t)(b * O_ + o0)) * I_;
    const float* xb = x + (size_t)b * I_ * L_;

    const int aRow0 = tid >> 2, aC = tid & 3;     // A: pass r -> row aRow0 + 64*r
    const int xRow0 = tid >> 5;                   // X: pass r -> row xRow0 + 8*r
    const int xCol = (tid & 31) * 4;

    float acc[4][4][4] = {};
    float4 px[4];

    const uint32_t frow = lane & 15, fc8 = (lane >> 4) * 8;

#define CP_A(k0, base) do { \
        const int koff = (k0); \
        _Pragma("unroll") \
        for (int r = 0; r < 2; r++) { \
            const int row = aRow0 + 64 * r; \
            const uint32_t d = sb + (base) + ST_A + row * (PA * 2) + aC * 16; \
            CP_ASYNC16(d, (const char*)(AG + (size_t)row * I_ + koff + aC * 8)); \
        } \
        CP_ASYNC_COMMIT(); \
    } while (0)

#define LDG_X(k0) do { \
        _Pragma("unroll") \
        for (int r = 0; r < 4; r++) \
            px[r] = *(const float4*)&xb[(size_t)((k0) + xRow0 + 8 * r) * L_ + l0 + xCol]; \
    } while (0)

#define STS_X(base) do { \
        _Pragma("unroll") \
        for (int r = 0; r < 4; r++) { \
            const int row = xRow0 + 8 * r; \
            const __half hx = __float2half_rn(px[r].x), hy = __float2half_rn(px[r].y); \
            const __half hz = __float2half_rn(px[r].z), hw = __float2half_rn(px[r].w); \
            uint2 hv; \
            hv.x = (uint32_t)__half_as_ushort(hx) | ((uint32_t)__half_as_ushort(hy) << 16); \
            hv.y = (uint32_t)__half_as_ushort(hz) | ((uint32_t)__half_as_ushort(hw) << 16); \
            *(uint2*)(smem + (base) + ST_X + row * (PX * 2) + xCol * 2) = hv; \
        } \
    } while (0)

    // prologue: chunk 0 into stage 0
    LDG_X(0);
    CP_A(0, 0);
    STS_X(0);
    CP_ASYNC_WAIT0();
    __syncthreads();

    #pragma unroll 1
    for (int c = 0; c < I_ / 32; c++) {
        const uint32_t cur = (uint32_t)(c & 1) * STAGE_SZ;
        const uint32_t nxt = (uint32_t)(1 - (c & 1)) * STAGE_SZ;
        const bool has_next = (c < I_ / 32 - 1);

        if (has_next) {
            CP_A((c + 1) * 32, nxt);   // async, overlaps compute below
            LDG_X((c + 1) * 32);
        }

        #pragma unroll
        for (int ks = 0; ks < 2; ks++) {
            uint32_t ah[4][4], bh[2][4];
            #pragma unroll
            for (int mi = 0; mi < 4; mi++) {
                const uint32_t ad = sb + cur + ST_A
                    + (m0w + mi * 16 + frow) * (PA * 2) + (ks * 16 + fc8) * 2;
                LDSM4(ah[mi], ad);
            }
            #pragma unroll
            for (int np = 0; np < 2; np++) {
                const uint32_t bd = sb + cur + ST_X
                    + (ks * 16 + frow) * (PX * 2) + (n0w + np * 16 + fc8) * 2;
                LDSM4T(bh[np], bd);
            }
            #pragma unroll
            for (int mi = 0; mi < 4; mi++) {
                #pragma unroll
                for (int nt = 0; nt < 4; nt++) {
                    const int np = nt >> 1, hp = (nt & 1) * 2;
                    MMA_F16(acc[mi][nt], ah[mi], bh[np][hp], bh[np][hp + 1]);
                }
            }
        }

        if (has_next) STS_X(nxt);
        CP_ASYNC_WAIT0();
        __syncthreads();
    }

    // epilogue
    const int g = lane >> 2, c2 = (lane & 3) * 2;
    #pragma unroll
    for (int mi = 0; mi < 4; mi++) {
        #pragma unroll
        for (int nt = 0; nt < 4; nt++) {
            const int o = o0 + m0w + mi * 16 + g;
            const int l = l0 + n0w + nt * 8 + c2;
            float* p = out + ((size_t)(b * O_ + o)) * L_ + l;
            float2 v0 = {acc[mi][nt][0], acc[mi][nt][1]};
            float2 v1 = {acc[mi][nt][2], acc[mi][nt][3]};
            *(float2*)p = v0;
            *(float2*)(p + 8 * L_) = v1;
        }
    }
#undef CP_A
#undef LDG_X
#undef STS_X
}

// ---------------------------------------------------------------------------
extern "C" void kernel_launch(void* const* d_in, const int* in_sizes, int n_in,
                              void* d_out, int out_size) {
    const float* x      = (const float*)d_in[0];
    const float* t      = (const float*)d_in[1];
    const float* weight = (const float*)d_in[2];
    const float* W1     = (const float*)d_in[3];
    const float* b1     = (const float*)d_in[4];
    const float* W2     = (const float*)d_in[5];
    const float* b2     = (const float*)d_in[6];
    const float* W3     = (const float*)d_in[7];
    const float* b3     = (const float*)d_in[8];
    float* out = (float*)d_out;

    cudaFuncSetAttribute(gemm_mma, cudaFuncAttributeMaxDynamicSharedMemorySize, SMEM_GEMM);

    float* h1 = nullptr; float* h2 = nullptr; float* s = nullptr;
    cudaGetSymbolAddress((void**)&h1, g_h1);
    cudaGetSymbolAddress((void**)&h2, g_h2);
    cudaGetSymbolAddress((void**)&s,  g_s);

    lin_kernel<<<dim3(T_ / 8, B_), 256>>>(t,  W1, b1, h1, T_, 1, 0.0f);
    lin_kernel<<<dim3(T_ / 8, B_), 256>>>(h1, W2, b2, h2, T_, 1, 0.0f);
    lin_kernel<<<dim3(I_ / 8, B_), 256>>>(h2, W3, b3, s,  I_, 0, 1.0f);
    demod_kernel<<<dim3(O_, B_), 128>>>(weight);
    gemm_mma<<<dim3(L_ / 128, O_ / 128, B_), 256, SMEM_GEMM>>>(x, out);
}

// round 8
// speedup vs baseline: 5.9096x; 1.0811x over previous
#include <cuda_runtime.h>
#include <cuda_fp16.h>
#include <cstdint>
#include <math.h>

#define B_ 16
#define I_ 512
#define O_ 512
#define T_ 256
#define L_ 4096
#define EPS_ 1e-8f

// ---------------------------------------------------------------------------
// Scratch
// ---------------------------------------------------------------------------
__device__ float g_s[B_ * I_];
__device__ float g_h1[B_ * T_];
__device__ float g_h2[B_ * T_];
__device__ __half g_bw[B_ * O_ * I_];      // 8 MB, demodulated weights fp16

// ---------------------------------------------------------------------------
// Helpers
// ---------------------------------------------------------------------------
__device__ __forceinline__ uint32_t smem_u32(const void* p) {
    uint32_t a;
    asm("{ .reg .u64 t; cvta.to.shared.u64 t, %1; cvt.u32.u64 %0, t; }" : "=r"(a) : "l"(p));
    return a;
}

#define LDSM4(r, addr) \
    asm volatile("ldmatrix.sync.aligned.m8n8.x4.shared.b16 {%0,%1,%2,%3}, [%4];" \
        : "=r"((r)[0]), "=r"((r)[1]), "=r"((r)[2]), "=r"((r)[3]) : "r"(addr))

#define LDSM4T(r, addr) \
    asm volatile("ldmatrix.sync.aligned.m8n8.x4.trans.shared.b16 {%0,%1,%2,%3}, [%4];" \
        : "=r"((r)[0]), "=r"((r)[1]), "=r"((r)[2]), "=r"((r)[3]) : "r"(addr))

#define MMA_F16(acc, a, b0, b1) \
    asm volatile("mma.sync.aligned.m16n8k16.row.col.f32.f16.f16.f32 " \
        "{%0,%1,%2,%3}, {%4,%5,%6,%7}, {%8,%9}, {%0,%1,%2,%3};" \
        : "+f"((acc)[0]), "+f"((acc)[1]), "+f"((acc)[2]), "+f"((acc)[3]) \
        : "r"((a)[0]), "r"((a)[1]), "r"((a)[2]), "r"((a)[3]), "r"(b0), "r"(b1))

#define CP_ASYNC16(smem_addr, gptr) \
    asm volatile("cp.async.cg.shared.global [%0], [%1], 16;" :: "r"(smem_addr), "l"(gptr))
#define CP_ASYNC_COMMIT() asm volatile("cp.async.commit_group;" ::: "memory")
#define CP_ASYNC_WAIT0()  asm volatile("cp.async.wait_group 0;" ::: "memory")
#define CP_ASYNC_WAIT1()  asm volatile("cp.async.wait_group 1;" ::: "memory")

// ---------------------------------------------------------------------------
// Kernel 1: one linear layer, one warp per output. grid = (out_dim/8, B).
// ---------------------------------------------------------------------------
__global__ void lin_kernel(const float* __restrict__ in, const float* __restrict__ W,
                           const float* __restrict__ bias, float* __restrict__ out,
                           int out_dim, int do_silu, float add_const) {
    const int b = blockIdx.y;
    const int wid = threadIdx.x >> 5, lid = threadIdx.x & 31;
    const int j = blockIdx.x * 8 + wid;

    const float* inv = in + b * T_;
    const float* wrow = W + j * T_;
    float acc = 0.0f;
    #pragma unroll
    for (int u = 0; u < T_ / 32; u++)
        acc += inv[lid + u * 32] * wrow[lid + u * 32];
    #pragma unroll
    for (int off = 16; off > 0; off >>= 1) acc += __shfl_xor_sync(0xFFFFFFFFu, acc, off);
    if (lid == 0) {
        float z = acc + bias[j] + add_const;
        out[b * out_dim + j] = do_silu ? z / (1.0f + expf(-z)) : z;
    }
}

// ---------------------------------------------------------------------------
// Kernel 2: demodulation -> fp16 weights, K-major [b][o][i].
// ---------------------------------------------------------------------------
__global__ void demod_kernel(const float* __restrict__ weight) {
    const int o = blockIdx.x, b = blockIdx.y;
    const int tid = threadIdx.x;  // 0..127
    const float* srow = g_s + b * I_;
    const float* wrow = weight + o * I_;

    float v[4];
    float ss = 0.0f;
    #pragma unroll
    for (int r = 0; r < 4; r++) {
        const int i = tid + r * 128;
        const float val = wrow[i] * srow[i];
        v[r] = val;
        ss += val * val;
    }
    #pragma unroll
    for (int off = 16; off > 0; off >>= 1) ss += __shfl_xor_sync(0xFFFFFFFFu, ss, off);
    __shared__ float red[4];
    if ((tid & 31) == 0) red[tid >> 5] = ss;
    __syncthreads();
    const float d = rsqrtf(red[0] + red[1] + red[2] + red[3] + EPS_);

    const size_t base = ((size_t)b * O_ + o) * I_;
    #pragma unroll
    for (int r = 0; r < 4; r++)
        g_bw[base + tid + r * 128] = __float2half_rn(v[r] * d);
}

// ---------------------------------------------------------------------------
// Kernel 3: mma.sync fp16 batched GEMM  out[b,o,l] = sum_i bw[b,o,i]*x[b,i,l]
// Block tile 128(M) x 128(N), K chunks of 32, 256 threads (8 warps),
// warp tile 64x32, single fp16 A, fp32 accum. 3-stage cp.async pipeline:
// at chunk c: STS_X(c+1) | cp.async A(c+2) | LDG_X(c+2) | compute(c).
// ---------------------------------------------------------------------------
#define PA 40                      // A smem pitch (fp16)  -> 80 B rows
#define PX 136                     // X smem pitch (fp16)  -> 272 B rows
#define A_BYTES (128 * PA * 2)     // 10240
#define X_BYTES (32 * PX * 2)      // 8704
#define ST_A 0
#define ST_X (A_BYTES)
#define STAGE_SZ (A_BYTES + X_BYTES)           // 18944
#define NSTAGE 3
#define SMEM_GEMM (NSTAGE * STAGE_SZ)          // 56832
#define NCHUNK (I_ / 32)                       // 16

__global__ __launch_bounds__(256, 2)
void gemm_mma(const float* __restrict__ x, float* __restrict__ out) {
    extern __shared__ __align__(16) char smem[];
    const uint32_t sb = smem_u32(smem);
    const int tid = threadIdx.x, lane = tid & 31, wid = tid >> 5;
    const int b = blockIdx.z, o0 = blockIdx.y * 128, l0 = blockIdx.x * 128;
    const int m0w = (wid & 1) * 64;    // warp m origin (2 warps in M)
    const int n0w = (wid >> 1) * 32;   // warp n origin (4 warps in N)

    const __half* AG = g_bw + ((size_t)(b * O_ + o0)) * I_;
    const float* xb = x + (size_t)b * I_ * L_;

    const int aRow0 = tid >> 2, aC = tid & 3;     // A: pass r -> row aRow0 + 64*r
    const int xRow0 = tid >> 5;                   // X: pass r -> row xRow0 + 8*r
    const int xCol = (tid & 31) * 4;

    float acc[4][4][4] = {};
    float4 px[4];

    const uint32_t frow = lane & 15, fc8 = (lane >> 4) * 8;

#define CP_A(k0, base) do { \
        const int koff = (k0); \
        _Pragma("unroll") \
        for (int r = 0; r < 2; r++) { \
            const int row = aRow0 + 64 * r; \
            const uint32_t d = sb + (base) + ST_A + row * (PA * 2) + aC * 16; \
            CP_ASYNC16(d, (const char*)(AG + (size_t)row * I_ + koff + aC * 8)); \
        } \
        CP_ASYNC_COMMIT(); \
    } while (0)

#define LDG_X(k0) do { \
        _Pragma("unroll") \
        for (int r = 0; r < 4; r++) \
            px[r] = *(const float4*)&xb[(size_t)((k0) + xRow0 + 8 * r) * L_ + l0 + xCol]; \
    } while (0)

#define STS_X(base) do { \
        _Pragma("unroll") \
        for (int r = 0; r < 4; r++) { \
            const int row = xRow0 + 8 * r; \
            const __half hx = __float2half_rn(px[r].x), hy = __float2half_rn(px[r].y); \
            const __half hz = __float2half_rn(px[r].z), hw = __float2half_rn(px[r].w); \
            uint2 hv; \
            hv.x = (uint32_t)__half_as_ushort(hx) | ((uint32_t)__half_as_ushort(hy) << 16); \
            hv.y = (uint32_t)__half_as_ushort(hz) | ((uint32_t)__half_as_ushort(hw) << 16); \
            *(uint2*)(smem + (base) + ST_X + row * (PX * 2) + xCol * 2) = hv; \
        } \
    } while (0)

    // --- prologue ---
    // X(0) staged directly; A(0), A(1) in flight; px holds X(1).
    LDG_X(0);
    STS_X(0 * STAGE_SZ);
    CP_A(0, 0 * STAGE_SZ);
    CP_A(32, 1 * STAGE_SZ);
    LDG_X(32);
    CP_ASYNC_WAIT1();      // A(0) landed (A(1) may still fly)
    __syncthreads();

    #pragma unroll 1
    for (int c = 0; c < NCHUNK; c++) {
        const uint32_t cur = (uint32_t)(c % NSTAGE) * STAGE_SZ;
        const uint32_t st1 = (uint32_t)((c + 1) % NSTAGE) * STAGE_SZ;
        const uint32_t st2 = (uint32_t)((c + 2) % NSTAGE) * STAGE_SZ;

        if (c + 1 < NCHUNK) STS_X(st1);            // px = X(c+1) from last iter
        if (c + 2 < NCHUNK) {
            CP_A((c + 2) * 32, st2);               // async, 2 ahead
            LDG_X((c + 2) * 32);                   // latency hidden by compute(c)
        }

        #pragma unroll
        for (int ks = 0; ks < 2; ks++) {
            uint32_t ah[4][4], bh[2][4];
            #pragma unroll
            for (int mi = 0; mi < 4; mi++) {
                const uint32_t ad = sb + cur + ST_A
                    + (m0w + mi * 16 + frow) * (PA * 2) + (ks * 16 + fc8) * 2;
                LDSM4(ah[mi], ad);
            }
            #pragma unroll
            for (int np = 0; np < 2; np++) {
                const uint32_t bd = sb + cur + ST_X
                    + (ks * 16 + frow) * (PX * 2) + (n0w + np * 16 + fc8) * 2;
                LDSM4T(bh[np], bd);
            }
            #pragma unroll
            for (int mi = 0; mi < 4; mi++) {
                #pragma unroll
                for (int nt = 0; nt < 4; nt++) {
                    const int np = nt >> 1, hp = (nt & 1) * 2;
                    MMA_F16(acc[mi][nt], ah[mi], bh[np][hp], bh[np][hp + 1]);
                }
            }
        }

        if (c + 2 < NCHUNK) CP_ASYNC_WAIT1();      // A(c+1) landed
        else                CP_ASYNC_WAIT0();
        __syncthreads();
    }

    // epilogue
    const int g = lane >> 2, c2 = (lane & 3) * 2;
    #pragma unroll
    for (int mi = 0; mi < 4; mi++) {
        #pragma unroll
        for (int nt = 0; nt < 4; nt++) {
            const int o = o0 + m0w + mi * 16 + g;
            const int l = l0 + n0w + nt * 8 + c2;
            float* p = out + ((size_t)(b * O_ + o)) * L_ + l;
            float2 v0 = {acc[mi][nt][0], acc[mi][nt][1]};
            float2 v1 = {acc[mi][nt][2], acc[mi][nt][3]};
            *(float2*)p = v0;
            *(float2*)(p + 8 * L_) = v1;
        }
    }
#undef CP_A
#undef LDG_X
#undef STS_X
}

// ---------------------------------------------------------------------------
extern "C" void kernel_launch(void* const* d_in, const int* in_sizes, int n_in,
                              void* d_out, int out_size) {
    const float* x      = (const float*)d_in[0];
    const float* t      = (const float*)d_in[1];
    const float* weight = (const float*)d_in[2];
    const float* W1     = (const float*)d_in[3];
    const float* b1     = (const float*)d_in[4];
    const float* W2     = (const float*)d_in[5];
    const float* b2     = (const float*)d_in[6];
    const float* W3     = (const float*)d_in[7];
    const float* b3     = (const float*)d_in[8];
    float* out = (float*)d_out;

    cudaFuncSetAttribute(gemm_mma, cudaFuncAttributeMaxDynamicSharedMemorySize, SMEM_GEMM);

    float* h1 = nullptr; float* h2 = nullptr; float* s = nullptr;
    cudaGetSymbolAddress((void**)&h1, g_h1);
    cudaGetSymbolAddress((void**)&h2, g_h2);
    cudaGetSymbolAddress((void**)&s,  g_s);

    lin_kernel<<<dim3(T_ / 8, B_), 256>>>(t,  W1, b1, h1, T_, 1, 0.0f);
    lin_kernel<<<dim3(T_ / 8, B_), 256>>>(h1, W2, b2, h2, T_, 1, 0.0f);
    lin_kernel<<<dim3(I_ / 8, B_), 256>>>(h2, W3, b3, s,  I_, 0, 1.0f);
    demod_kernel<<<dim3(O_, B_), 128>>>(weight);
    gemm_mma<<<dim3(L_ / 128, O_ / 128, B_), 256, SMEM_GEMM>>>(x, out);
}